// round 14
// baseline (speedup 1.0000x reference)
#include <cuda_runtime.h>
#include <cuda_bf16.h>
#include <cstdint>

#define NTOK 8192
#define EDIM 64
#define SCALE 0.35355339059327373f    // 1/sqrt(8)
#define NPART 2

// packed bf16x2 words: [row][32 words], SW128-swizzled 16B chunks within 128B rows.
__device__ uint32_t g_qh[NTOK*32];
__device__ uint32_t g_kh[NTOK*32];
__device__ uint32_t g_vh[NTOK*32];
__device__ float    g_opart[NPART][NTOK][EDIM];   // unnormalized O per KV-part
__device__ float    g_lpart[NPART][NTOK];         // softmax denominator per KV-part

// ======================= helpers =======================
__device__ __forceinline__ uint32_t smem_u32(const void* p) {
    uint32_t a;
    asm("{ .reg .u64 t; cvta.to.shared.u64 t, %1; cvt.u32.u64 %0, t; }" : "=r"(a) : "l"(p));
    return a;
}
__device__ __forceinline__ void cp16(uint32_t dst, const void* src) {
    asm volatile("{ .reg .u64 g; cvta.to.global.u64 g, %1; cp.async.cg.shared.global [%0], [g], 16; }"
                 :: "r"(dst), "l"(src) : "memory");
}
#define CP_COMMIT() asm volatile("cp.async.commit_group;" ::: "memory")
#define CP_WAIT(n)  asm volatile("cp.async.wait_group %0;" :: "n"(n) : "memory")

#define LDSM4(r, a) \
    asm volatile("ldmatrix.sync.aligned.m8n8.x4.shared.b16 {%0,%1,%2,%3}, [%4];" \
        : "=r"((r)[0]), "=r"((r)[1]), "=r"((r)[2]), "=r"((r)[3]) : "r"(a))
#define LDSM4T(r, a) \
    asm volatile("ldmatrix.sync.aligned.m8n8.x4.trans.shared.b16 {%0,%1,%2,%3}, [%4];" \
        : "=r"((r)[0]), "=r"((r)[1]), "=r"((r)[2]), "=r"((r)[3]) : "r"(a))

#define MMA(c, a, b0, b1) \
    asm volatile("mma.sync.aligned.m16n8k16.row.col.f32.bf16.bf16.f32 " \
        "{%0,%1,%2,%3}, {%4,%5,%6,%7}, {%8,%9}, {%0,%1,%2,%3};" \
        : "+f"((c)[0]), "+f"((c)[1]), "+f"((c)[2]), "+f"((c)[3]) \
        : "r"((a)[0]), "r"((a)[1]), "r"((a)[2]), "r"((a)[3]), "r"(b0), "r"(b1))

// swizzled smem address: 128B rows, 16B chunk index XOR (row&7)
__device__ __forceinline__ uint32_t swadr(uint32_t base, int row, int bytecol) {
    return base + row*128 + ((((bytecol >> 4) ^ (row & 7)) << 4));
}
__device__ __forceinline__ uint32_t pack2(float a, float b) {
    __nv_bfloat162 p = __floats2bfloat162_rn(a, b);    // x=a (low), y=b (high)
    return *reinterpret_cast<uint32_t*>(&p);
}
#define STS128(addr, r0, r1, r2, r3) \
    asm volatile("st.shared.v4.b32 [%0], {%1,%2,%3,%4};" :: "r"(addr), "r"(r0), "r"(r1), "r"(r2), "r"(r3) : "memory")

// flash smem: Qh 0..8K ; buf b (b=0..2) at 8192 + b*16384 : [Kh 8K | Vh 8K]
#define SBUF(b)    (8192 + (b)*16384)
#define SMEM_FLASH 57344

// ---------------- Kernel 1: fused QKV projection via HMMA + quantum map + packing ----
// CTA = 64 rows x 32 cols x ALL THREE matrices. 256 thr (8 warps).
// x staged once; 3 independent MMA/epilogue chains give ILP.
__global__ void __launch_bounds__(256) qkv_kernel(
    const float* __restrict__ x,
    const float* __restrict__ wq, const float* __restrict__ bq,
    const float* __restrict__ wk, const float* __restrict__ bk,
    const float* __restrict__ wv, const float* __restrict__ bv,
    const float* __restrict__ theta)
{
    __shared__ __align__(16) char qsm[8192 + 3*4096];   // xb[64][128B] | wb[3][32][128B]
    __shared__ float bs[96];
    __shared__ float cs[96];
    uint32_t sb = smem_u32(qsm);
    const uint32_t wbase0 = sb + 8192;

    const int tid  = threadIdx.x;
    const int wid  = tid >> 5;
    const int lane = tid & 31;
    const int row0 = blockIdx.x * 64;
    const int c0g  = blockIdx.y * 32;

    const float* wmat[3] = {wq, wk, wv};
    const float* bvec[3] = {bq, bk, bv};

    // ---- stage x rows row0..row0+63: thread = row tid>>2, cols (tid&3)*16 ----
    {
        const int r  = tid >> 2;            // 0..63
        const int c0 = (tid & 3) * 16;
        const float* xr = x + (size_t)(row0 + r)*64 + c0;
        uint32_t wd[8];
        #pragma unroll
        for (int j = 0; j < 8; j++) wd[j] = pack2(xr[2*j], xr[2*j + 1]);
        #pragma unroll
        for (int q = 0; q < 2; q++) {
            int ch = (((c0 >> 3) + q) ^ (r & 7));
            STS128(sb + r*128 + ch*16, wd[4*q], wd[4*q+1], wd[4*q+2], wd[4*q+3]);
        }
    }
    // ---- stage w[m] rows c0g..c0g+31: thread = wrow tid>>3, cols (tid&7)*8 ----
    #pragma unroll
    for (int m = 0; m < 3; m++) {
        const int r  = tid >> 3;            // 0..31
        const int c0 = (tid & 7) * 8;
        const float* wr = wmat[m] + (size_t)(c0g + r)*64 + c0;
        uint32_t wd[4];
        #pragma unroll
        for (int j = 0; j < 4; j++) wd[j] = pack2(wr[2*j], wr[2*j + 1]);
        int ch = ((c0 >> 3) ^ (r & 7));
        STS128(wbase0 + m*4096 + r*128 + ch*16, wd[0], wd[1], wd[2], wd[3]);
    }
    if (tid < 96) {
        const int m = tid >> 5, c = tid & 31;
        bs[tid] = bvec[m][c0g + c];
        cs[tid] = ((m == 0) ? SCALE : 1.0f) * __cosf(theta[c0g + c]);
    }
    __syncthreads();

    const int kg  = wid >> 2;       // col half of the 32-col slab
    const int wq4 = wid & 3;        // row quarter

    // ---- A fragments (shared across all 3 matrices) ----
    uint32_t qa[4][4];
    {
        const int row = wq4*16 + (lane & 15);
        const int cb  = (lane >> 4) * 16;
        #pragma unroll
        for (int kc = 0; kc < 4; kc++)
            LDSM4(qa[kc], swadr(sb, row, 32*kc + cb));
    }

    const int li = lane & 7, ls = lane >> 3;
    const int gq = lane >> 2, t = lane & 3;
    const int r0 = row0 + wq4*16 + gq;
    const int r1 = r0 + 8;

    #pragma unroll
    for (int m = 0; m < 3; m++) {
        const uint32_t wbase = wbase0 + m*4096;

        float sc[2][4];
        #pragma unroll
        for (int nbl = 0; nbl < 2; nbl++)
            #pragma unroll
            for (int tt = 0; tt < 4; tt++) sc[nbl][tt] = 0.f;

        #pragma unroll
        for (int nbl = 0; nbl < 2; nbl++) {
            const int nb = kg*2 + nbl;
            #pragma unroll
            for (int kcp = 0; kcp < 2; kcp++) {
                uint32_t kf[4];
                LDSM4(kf, swadr(wbase, nb*8 + li, 64*kcp + ls*16));
                MMA(sc[nbl], qa[kcp*2 + 0], kf[0], kf[1]);
                MMA(sc[nbl], qa[kcp*2 + 1], kf[2], kf[3]);
            }
        }

        uint32_t* dst = (m == 0) ? g_qh : ((m == 1) ? g_kh : g_vh);
        #pragma unroll
        for (int nbl = 0; nbl < 2; nbl++) {
            const int cl = (kg*2 + nbl)*8 + 2*t;       // local col 0..31
            const int chunk = (c0g >> 3) + kg*2 + nbl; // global 16B chunk 0..7
            float v0 = cs[m*32 + cl]     * __cosf(sc[nbl][0] + bs[m*32 + cl]);
            float v1 = cs[m*32 + cl + 1] * __cosf(sc[nbl][1] + bs[m*32 + cl + 1]);
            float v2 = cs[m*32 + cl]     * __cosf(sc[nbl][2] + bs[m*32 + cl]);
            float v3 = cs[m*32 + cl + 1] * __cosf(sc[nbl][3] + bs[m*32 + cl + 1]);
            dst[(size_t)r0*32 + ((chunk ^ (r0 & 7)) << 2) + t] = pack2(v0, v1);
            dst[(size_t)r1*32 + ((chunk ^ (r1 & 7)) << 2) + t] = pack2(v2, v3);
        }
    }
}

// ---------------- tile copy: 64 keys x (Kh, Vh), pre-swizzled ----------------
__device__ __forceinline__ void copy_tile(uint32_t sb, int tid, int buf, int kt) {
    #pragma unroll
    for (int j = 0; j < 4; j++) {
        int c = j*256 + tid;        // 0..1023
        int arr = c >> 9;           // 0:kh 1:vh (constant per j)
        int rem = c & 511;
        int row = rem >> 3, ch = rem & 7;
        const uint32_t* sp = arr ? g_vh : g_kh;
        cp16(sb + SBUF(buf) + arr*8192 + row*128 + ch*16,
             sp + (size_t)(kt*64 + row)*32 + ch*4);
    }
}

// ---------------- Kernel 2: bf16 flash attention, split-KV x2 (R10 structure) -------
__global__ void __launch_bounds__(256, 2) flash_kernel()
{
    extern __shared__ char smem[];
    uint32_t sb = smem_u32(smem);
    const int tid  = threadIdx.x;
    const int wid  = tid >> 5;
    const int lane = tid & 31;
    const int qb   = blockIdx.x >> 1;       // 64 q-rows per CTA
    const int part = blockIdx.x & 1;        // KV half: tiles part*64 .. +63
    const int kt0  = part * 64;
    const int kg   = wid >> 2;              // key group: 0 -> keys 0-31, 1 -> keys 32-63
    const int wq4  = wid & 3;               // q-row quarter: rows wq4*16..+15

    // ---- prologue copies: Qh, tiles 0,1 ----
    #pragma unroll
    for (int j = 0; j < 2; j++) {
        int c = j*256 + tid;
        int row = c >> 3, ch = c & 7;
        cp16(sb + row*128 + ch*16, g_qh + (size_t)(qb*64 + row)*32 + ch*4);
    }
    CP_COMMIT();
    copy_tile(sb, tid, 0, kt0 + 0); CP_COMMIT();
    copy_tile(sb, tid, 1, kt0 + 1); CP_COMMIT();
    CP_WAIT(2);                  // Q landed
    __syncthreads();

    // ---- Q A-fragments (persistent) ----
    uint32_t qh[4][4];
    {
        const int row = wq4*16 + (lane & 15);
        const int cb  = (lane >> 4) * 16;
        #pragma unroll
        for (int kc = 0; kc < 4; kc++)
            LDSM4(qh[kc], swadr(sb, row, 32*kc + cb));
    }

    float o[8][4];
    #pragma unroll
    for (int db = 0; db < 8; db++)
        #pragma unroll
        for (int i = 0; i < 4; i++) o[db][i] = 0.f;
    float lg = 0.f, lg8 = 0.f;

    const int li = lane & 7, ls = lane >> 3;
    const int lr = (lane >> 3) & 1, lc = lane >> 4;
    const int nb0 = kg * 4;

    int b = 0;
    #pragma unroll 1
    for (int kb = 0; kb < 64; kb++) {
        CP_WAIT(1);              // tile kb landed (kb+1 may be in flight)
        __syncthreads();         // all warps past tile kb-1; kb visible everywhere
        if (kb + 2 < 64) {       // refill the buffer freed by tile kb-1
            int nbuf = (b == 2) ? 0 : b + 1;
            int pbuf = (nbuf == 2) ? 0 : nbuf + 1;   // (kb+2)%3
            copy_tile(sb, tid, pbuf, kt0 + kb + 2); CP_COMMIT();
        }

        const uint32_t kbh = sb + SBUF(b);
        const uint32_t vbh = kbh + 8192;

        // ---- S = qh . kh over this group's 32 keys ----
        float sc[4][4];
        #pragma unroll
        for (int ln = 0; ln < 4; ln++)
            #pragma unroll
            for (int t = 0; t < 4; t++) sc[ln][t] = 0.f;

        #pragma unroll
        for (int ln = 0; ln < 4; ln++) {
            const int nb = nb0 + ln;
            #pragma unroll
            for (int kcp = 0; kcp < 2; kcp++) {
                uint32_t kf[4];
                LDSM4(kf, swadr(kbh, nb*8 + li, 64*kcp + ls*16));
                MMA(sc[ln], qh[kcp*2 + 0], kf[0], kf[1]);
                MMA(sc[ln], qh[kcp*2 + 1], kf[2], kf[3]);
            }
        }

        // ---- exp (no max; bounded scores) + pack P ----
        uint32_t ph[2][4];
        #pragma unroll
        for (int ln = 0; ln < 4; ln++) {
            float e0 = __expf(sc[ln][0]), e1 = __expf(sc[ln][1]);
            float e2 = __expf(sc[ln][2]), e3 = __expf(sc[ln][3]);
            lg  += e0 + e1;
            lg8 += e2 + e3;
            const int kcl = ln >> 1, rb = (ln & 1) * 2;
            ph[kcl][rb + 0] = pack2(e0, e1);
            ph[kcl][rb + 1] = pack2(e2, e3);
        }

        // ---- O += P V over this group's 32 keys ----
        #pragma unroll
        for (int kcl = 0; kcl < 2; kcl++) {
            const int kcg = kg*2 + kcl;
            uint32_t vf[4][4];
            #pragma unroll
            for (int dp = 0; dp < 4; dp++)
                LDSM4T(vf[dp], swadr(vbh, kcg*16 + lr*8 + li, 32*dp + lc*16));
            #pragma unroll
            for (int db = 0; db < 8; db++)
                MMA(o[db], ph[kcl], vf[db>>1][(db&1)*2], vf[db>>1][(db&1)*2+1]);
        }

        b = (b == 2) ? 0 : b + 1;
    }

    // ---- reduce l within quad ----
    lg  += __shfl_xor_sync(0xffffffffu, lg, 1);
    lg  += __shfl_xor_sync(0xffffffffu, lg, 2);
    lg8 += __shfl_xor_sync(0xffffffffu, lg8, 1);
    lg8 += __shfl_xor_sync(0xffffffffu, lg8, 2);

    // ---- cross-keygroup reduction via smem (buffers are free now) ----
    float* red  = (float*)(smem + 8192);             // [4][32][32] = 16KB
    float* redl = (float*)(smem + 8192 + 16384);     // [4][32][2]
    __syncthreads();
    if (kg == 1) {
        float* dst = red + (wq4*32 + lane)*32;
        #pragma unroll
        for (int db = 0; db < 8; db++)
            #pragma unroll
            for (int t = 0; t < 4; t++) dst[db*4 + t] = o[db][t];
        redl[(wq4*32 + lane)*2 + 0] = lg;
        redl[(wq4*32 + lane)*2 + 1] = lg8;
    }
    __syncthreads();
    if (kg == 0) {
        const float* src = red + (wq4*32 + lane)*32;
        #pragma unroll
        for (int db = 0; db < 8; db++)
            #pragma unroll
            for (int t = 0; t < 4; t++) o[db][t] += src[db*4 + t];
        lg  += redl[(wq4*32 + lane)*2 + 0];
        lg8 += redl[(wq4*32 + lane)*2 + 1];

        const int gq = lane >> 2, t = lane & 3;
        const int n = qb*64 + wq4*16 + gq;
        #pragma unroll
        for (int db = 0; db < 8; db++) {
            int d = db*8 + 2*t;
            *reinterpret_cast<float2*>(&g_opart[part][n][d])     = make_float2(o[db][0], o[db][1]);
            *reinterpret_cast<float2*>(&g_opart[part][n + 8][d]) = make_float2(o[db][2], o[db][3]);
        }
        if (t == 0) {
            g_lpart[part][n]     = lg;
            g_lpart[part][n + 8] = lg8;
        }
    }
}

// ---------------- Kernel 3: combine halves + output projection (64-row CTAs) --------
__global__ void __launch_bounds__(256) proj_kernel(
    const float* __restrict__ wo, const float* __restrict__ bo,
    float* __restrict__ out)
{
    __shared__ float wtT[64*64];   // [d][col] transposed for broadcast float4
    __shared__ float os[64*65];    // combined+normalized O, stride 65
    __shared__ float bs[64];
    __shared__ float linv[64];
    const int tid = threadIdx.x;
    const int row0 = blockIdx.x * 64;

    for (int i = tid; i < 4096; i += 256) {
        int col = i >> 6, d = i & 63;
        wtT[d*64 + col] = wo[(size_t)col*64 + d];
    }
    if (tid < 64) {
        bs[tid] = bo[tid];
        int n = row0 + tid;
        linv[tid] = 1.0f / (g_lpart[0][n] + g_lpart[1][n]);
    }
    __syncthreads();
    for (int i = tid; i < 4096; i += 256) {
        int row = i >> 6, d = i & 63;
        int n = row0 + row;
        os[row*65 + d] = (g_opart[0][n][d] + g_opart[1][n][d]) * linv[row];
    }
    __syncthreads();

    const int rg = tid & 63;            // row
    const int c0 = (tid >> 6) * 16;     // warp-uniform column block

    float acc[16];
    #pragma unroll
    for (int j = 0; j < 16; j++) acc[j] = bs[c0 + j];

    #pragma unroll 8
    for (int d = 0; d < 64; d++) {
        float xv = os[rg*65 + d];
        #pragma unroll
        for (int q = 0; q < 4; q++) {
            float4 wv = *reinterpret_cast<float4*>(&wtT[d*64 + c0 + q*4]);   // broadcast
            acc[q*4 + 0] = fmaf(xv, wv.x, acc[q*4 + 0]);
            acc[q*4 + 1] = fmaf(xv, wv.y, acc[q*4 + 1]);
            acc[q*4 + 2] = fmaf(xv, wv.z, acc[q*4 + 2]);
            acc[q*4 + 3] = fmaf(xv, wv.w, acc[q*4 + 3]);
        }
    }

    float* op = &out[(size_t)(row0 + rg)*64 + c0];
    #pragma unroll
    for (int q = 0; q < 4; q++)
        *reinterpret_cast<float4*>(op + q*4) =
            make_float4(acc[q*4], acc[q*4+1], acc[q*4+2], acc[q*4+3]);
}

// ---------------- launch ----------------
extern "C" void kernel_launch(void* const* d_in, const int* in_sizes, int n_in,
                              void* d_out, int out_size)
{
    const float* x  = (const float*)d_in[0];
    const float* wq = (const float*)d_in[1];
    const float* bq = (const float*)d_in[2];
    const float* wk = (const float*)d_in[3];
    const float* bk = (const float*)d_in[4];
    const float* wv = (const float*)d_in[5];
    const float* bv = (const float*)d_in[6];
    const float* th = (const float*)d_in[7];
    const float* wo = (const float*)d_in[8];
    const float* bo = (const float*)d_in[9];
    float* out = (float*)d_out;

    cudaFuncSetAttribute(flash_kernel, cudaFuncAttributeMaxDynamicSharedMemorySize, SMEM_FLASH);

    qkv_kernel<<<dim3(NTOK/64, 2), 256>>>(x, wq, bq, wk, bk, wv, bv, th);
    flash_kernel<<<256, 256, SMEM_FLASH>>>();
    proj_kernel<<<NTOK/64, 256>>>(wo, bo, out);
}

// round 15
// speedup vs baseline: 1.0255x; 1.0255x over previous
#include <cuda_runtime.h>
#include <cuda_bf16.h>
#include <cuda_fp16.h>
#include <cstdint>

#define NTOK 8192
#define EDIM 64
#define SCALE 0.35355339059327373f    // 1/sqrt(8)
#define NPART 2

// Q/K: packed fp16x2 words; V: packed bf16x2 words. [row][32 words], SW128-swizzled.
__device__ uint32_t g_qh[NTOK*32];
__device__ uint32_t g_kh[NTOK*32];
__device__ uint32_t g_vh[NTOK*32];
__device__ float    g_opart[NPART][NTOK][EDIM];   // unnormalized O per KV-part
__device__ float    g_lpart[NPART][NTOK];         // softmax denominator per KV-part

// ======================= helpers =======================
__device__ __forceinline__ uint32_t smem_u32(const void* p) {
    uint32_t a;
    asm("{ .reg .u64 t; cvta.to.shared.u64 t, %1; cvt.u32.u64 %0, t; }" : "=r"(a) : "l"(p));
    return a;
}
__device__ __forceinline__ void cp16(uint32_t dst, const void* src) {
    asm volatile("{ .reg .u64 g; cvta.to.global.u64 g, %1; cp.async.cg.shared.global [%0], [g], 16; }"
                 :: "r"(dst), "l"(src) : "memory");
}
#define CP_COMMIT() asm volatile("cp.async.commit_group;" ::: "memory")
#define CP_WAIT(n)  asm volatile("cp.async.wait_group %0;" :: "n"(n) : "memory")

#define LDSM4(r, a) \
    asm volatile("ldmatrix.sync.aligned.m8n8.x4.shared.b16 {%0,%1,%2,%3}, [%4];" \
        : "=r"((r)[0]), "=r"((r)[1]), "=r"((r)[2]), "=r"((r)[3]) : "r"(a))
#define LDSM4T(r, a) \
    asm volatile("ldmatrix.sync.aligned.m8n8.x4.trans.shared.b16 {%0,%1,%2,%3}, [%4];" \
        : "=r"((r)[0]), "=r"((r)[1]), "=r"((r)[2]), "=r"((r)[3]) : "r"(a))

// bf16 in, fp32 accum
#define MMA(c, a, b0, b1) \
    asm volatile("mma.sync.aligned.m16n8k16.row.col.f32.bf16.bf16.f32 " \
        "{%0,%1,%2,%3}, {%4,%5,%6,%7}, {%8,%9}, {%0,%1,%2,%3};" \
        : "+f"((c)[0]), "+f"((c)[1]), "+f"((c)[2]), "+f"((c)[3]) \
        : "r"((a)[0]), "r"((a)[1]), "r"((a)[2]), "r"((a)[3]), "r"(b0), "r"(b1))

// fp16 in, fp16 accum (2x rate hypothesis)
#define MMAH(c, a, b0, b1) \
    asm volatile("mma.sync.aligned.m16n8k16.row.col.f16.f16.f16.f16 " \
        "{%0,%1}, {%2,%3,%4,%5}, {%6,%7}, {%0,%1};" \
        : "+r"((c)[0]), "+r"((c)[1]) \
        : "r"((a)[0]), "r"((a)[1]), "r"((a)[2]), "r"((a)[3]), "r"(b0), "r"(b1))

// swizzled smem address: 128B rows, 16B chunk index XOR (row&7)
__device__ __forceinline__ uint32_t swadr(uint32_t base, int row, int bytecol) {
    return base + row*128 + ((((bytecol >> 4) ^ (row & 7)) << 4));
}
__device__ __forceinline__ uint32_t pack2(float a, float b) {     // bf16x2
    __nv_bfloat162 p = __floats2bfloat162_rn(a, b);
    return *reinterpret_cast<uint32_t*>(&p);
}
__device__ __forceinline__ uint32_t pack2h(float a, float b) {    // fp16x2
    __half2 p = __floats2half2_rn(a, b);
    return *reinterpret_cast<uint32_t*>(&p);
}
#define STS128(addr, r0, r1, r2, r3) \
    asm volatile("st.shared.v4.b32 [%0], {%1,%2,%3,%4};" :: "r"(addr), "r"(r0), "r"(r1), "r"(r2), "r"(r3) : "memory")

// flash smem: Qh 0..8K ; buf b (b=0..2) at 8192 + b*16384 : [Kh 8K | Vh 8K]
#define SBUF(b)    (8192 + (b)*16384)
#define SMEM_FLASH 57344

// ---------------- Kernel 1: fused QKV projection via HMMA + quantum map + packing ----
__global__ void __launch_bounds__(256) qkv_kernel(
    const float* __restrict__ x,
    const float* __restrict__ wq, const float* __restrict__ bq,
    const float* __restrict__ wk, const float* __restrict__ bk,
    const float* __restrict__ wv, const float* __restrict__ bv,
    const float* __restrict__ theta)
{
    __shared__ __align__(16) char qsm[8192 + 3*4096];   // xb[64][128B] | wb[3][32][128B]
    __shared__ float bs[96];
    __shared__ float cs[96];
    uint32_t sb = smem_u32(qsm);
    const uint32_t wbase0 = sb + 8192;

    const int tid  = threadIdx.x;
    const int wid  = tid >> 5;
    const int lane = tid & 31;
    const int row0 = blockIdx.x * 64;
    const int c0g  = blockIdx.y * 32;

    const float* wmat[3] = {wq, wk, wv};
    const float* bvec[3] = {bq, bk, bv};

    // ---- stage x rows row0..row0+63 (bf16) ----
    {
        const int r  = tid >> 2;            // 0..63
        const int c0 = (tid & 3) * 16;
        const float* xr = x + (size_t)(row0 + r)*64 + c0;
        uint32_t wd[8];
        #pragma unroll
        for (int j = 0; j < 8; j++) wd[j] = pack2(xr[2*j], xr[2*j + 1]);
        #pragma unroll
        for (int q = 0; q < 2; q++) {
            int ch = (((c0 >> 3) + q) ^ (r & 7));
            STS128(sb + r*128 + ch*16, wd[4*q], wd[4*q+1], wd[4*q+2], wd[4*q+3]);
        }
    }
    // ---- stage w[m] rows c0g..c0g+31 (bf16) ----
    #pragma unroll
    for (int m = 0; m < 3; m++) {
        const int r  = tid >> 3;            // 0..31
        const int c0 = (tid & 7) * 8;
        const float* wr = wmat[m] + (size_t)(c0g + r)*64 + c0;
        uint32_t wd[4];
        #pragma unroll
        for (int j = 0; j < 4; j++) wd[j] = pack2(wr[2*j], wr[2*j + 1]);
        int ch = ((c0 >> 3) ^ (r & 7));
        STS128(wbase0 + m*4096 + r*128 + ch*16, wd[0], wd[1], wd[2], wd[3]);
    }
    if (tid < 96) {
        const int m = tid >> 5, c = tid & 31;
        bs[tid] = bvec[m][c0g + c];
        cs[tid] = ((m == 0) ? SCALE : 1.0f) * __cosf(theta[c0g + c]);
    }
    __syncthreads();

    const int kg  = wid >> 2;       // col half of the 32-col slab
    const int wq4 = wid & 3;        // row quarter

    // ---- A fragments (shared across all 3 matrices) ----
    uint32_t qa[4][4];
    {
        const int row = wq4*16 + (lane & 15);
        const int cb  = (lane >> 4) * 16;
        #pragma unroll
        for (int kc = 0; kc < 4; kc++)
            LDSM4(qa[kc], swadr(sb, row, 32*kc + cb));
    }

    const int li = lane & 7, ls = lane >> 3;
    const int gq = lane >> 2, t = lane & 3;
    const int r0 = row0 + wq4*16 + gq;
    const int r1 = r0 + 8;

    #pragma unroll
    for (int m = 0; m < 3; m++) {
        const uint32_t wbase = wbase0 + m*4096;

        float sc[2][4];
        #pragma unroll
        for (int nbl = 0; nbl < 2; nbl++)
            #pragma unroll
            for (int tt = 0; tt < 4; tt++) sc[nbl][tt] = 0.f;

        #pragma unroll
        for (int nbl = 0; nbl < 2; nbl++) {
            const int nb = kg*2 + nbl;
            #pragma unroll
            for (int kcp = 0; kcp < 2; kcp++) {
                uint32_t kf[4];
                LDSM4(kf, swadr(wbase, nb*8 + li, 64*kcp + ls*16));
                MMA(sc[nbl], qa[kcp*2 + 0], kf[0], kf[1]);
                MMA(sc[nbl], qa[kcp*2 + 1], kf[2], kf[3]);
            }
        }

        uint32_t* dst = (m == 0) ? g_qh : ((m == 1) ? g_kh : g_vh);
        #pragma unroll
        for (int nbl = 0; nbl < 2; nbl++) {
            const int cl = (kg*2 + nbl)*8 + 2*t;       // local col 0..31
            const int chunk = (c0g >> 3) + kg*2 + nbl; // global 16B chunk 0..7
            float v0 = cs[m*32 + cl]     * __cosf(sc[nbl][0] + bs[m*32 + cl]);
            float v1 = cs[m*32 + cl + 1] * __cosf(sc[nbl][1] + bs[m*32 + cl + 1]);
            float v2 = cs[m*32 + cl]     * __cosf(sc[nbl][2] + bs[m*32 + cl]);
            float v3 = cs[m*32 + cl + 1] * __cosf(sc[nbl][3] + bs[m*32 + cl + 1]);
            uint32_t w0 = (m == 2) ? pack2(v0, v1) : pack2h(v0, v1);
            uint32_t w1 = (m == 2) ? pack2(v2, v3) : pack2h(v2, v3);
            dst[(size_t)r0*32 + ((chunk ^ (r0 & 7)) << 2) + t] = w0;
            dst[(size_t)r1*32 + ((chunk ^ (r1 & 7)) << 2) + t] = w1;
        }
    }
}

// ---------------- tile copy: 64 keys x (Kh fp16, Vh bf16), pre-swizzled --------------
__device__ __forceinline__ void copy_tile(uint32_t sb, int tid, int buf, int kt) {
    #pragma unroll
    for (int j = 0; j < 4; j++) {
        int c = j*256 + tid;        // 0..1023
        int arr = c >> 9;           // 0:kh 1:vh (constant per j)
        int rem = c & 511;
        int row = rem >> 3, ch = rem & 7;
        const uint32_t* sp = arr ? g_vh : g_kh;
        cp16(sb + SBUF(buf) + arr*8192 + row*128 + ch*16,
             sp + (size_t)(kt*64 + row)*32 + ch*4);
    }
}

// ---------------- Kernel 2: flash attention, fp16 S-path + bf16 PV, split-KV x2 -----
__global__ void __launch_bounds__(256, 2) flash_kernel()
{
    extern __shared__ char smem[];
    uint32_t sb = smem_u32(smem);
    const int tid  = threadIdx.x;
    const int wid  = tid >> 5;
    const int lane = tid & 31;
    const int qb   = blockIdx.x >> 1;       // 64 q-rows per CTA
    const int part = blockIdx.x & 1;        // KV half: tiles part*64 .. +63
    const int kt0  = part * 64;
    const int kg   = wid >> 2;              // key group: 0 -> keys 0-31, 1 -> keys 32-63
    const int wq4  = wid & 3;               // q-row quarter: rows wq4*16..+15

    // ---- prologue copies: Qh, tiles 0,1 ----
    #pragma unroll
    for (int j = 0; j < 2; j++) {
        int c = j*256 + tid;
        int row = c >> 3, ch = c & 7;
        cp16(sb + row*128 + ch*16, g_qh + (size_t)(qb*64 + row)*32 + ch*4);
    }
    CP_COMMIT();
    copy_tile(sb, tid, 0, kt0 + 0); CP_COMMIT();
    copy_tile(sb, tid, 1, kt0 + 1); CP_COMMIT();
    CP_WAIT(2);                  // Q landed
    __syncthreads();

    // ---- Q A-fragments (persistent, fp16 data) ----
    uint32_t qh[4][4];
    {
        const int row = wq4*16 + (lane & 15);
        const int cb  = (lane >> 4) * 16;
        #pragma unroll
        for (int kc = 0; kc < 4; kc++)
            LDSM4(qh[kc], swadr(sb, row, 32*kc + cb));
    }

    float o[8][4];
    #pragma unroll
    for (int db = 0; db < 8; db++)
        #pragma unroll
        for (int i = 0; i < 4; i++) o[db][i] = 0.f;
    float lg = 0.f, lg8 = 0.f;

    const int li = lane & 7, ls = lane >> 3;
    const int lr = (lane >> 3) & 1, lc = lane >> 4;
    const int nb0 = kg * 4;

    int b = 0;
    #pragma unroll 1
    for (int kb = 0; kb < 64; kb++) {
        CP_WAIT(1);              // tile kb landed (kb+1 may be in flight)
        __syncthreads();         // all warps past tile kb-1; kb visible everywhere
        if (kb + 2 < 64) {       // refill the buffer freed by tile kb-1
            int nbuf = (b == 2) ? 0 : b + 1;
            int pbuf = (nbuf == 2) ? 0 : nbuf + 1;   // (kb+2)%3
            copy_tile(sb, tid, pbuf, kt0 + kb + 2); CP_COMMIT();
        }

        const uint32_t kbh = sb + SBUF(b);
        const uint32_t vbh = kbh + 8192;

        // ---- S = q . k in full fp16 (fp16 accumulate) over this group's 32 keys ----
        uint32_t s16[4][2];
        #pragma unroll
        for (int ln = 0; ln < 4; ln++) { s16[ln][0] = 0u; s16[ln][1] = 0u; }

        #pragma unroll
        for (int ln = 0; ln < 4; ln++) {
            const int nb = nb0 + ln;
            #pragma unroll
            for (int kcp = 0; kcp < 2; kcp++) {
                uint32_t kf[4];
                LDSM4(kf, swadr(kbh, nb*8 + li, 64*kcp + ls*16));
                MMAH(s16[ln], qh[kcp*2 + 0], kf[0], kf[1]);
                MMAH(s16[ln], qh[kcp*2 + 1], kf[2], kf[3]);
            }
        }

        // ---- exp (no max; bounded scores) + pack P (bf16 for PV) ----
        uint32_t ph[2][4];
        #pragma unroll
        for (int ln = 0; ln < 4; ln++) {
            float2 f01 = __half22float2(*reinterpret_cast<__half2*>(&s16[ln][0]));
            float2 f23 = __half22float2(*reinterpret_cast<__half2*>(&s16[ln][1]));
            float e0 = __expf(f01.x), e1 = __expf(f01.y);
            float e2 = __expf(f23.x), e3 = __expf(f23.y);
            lg  += e0 + e1;
            lg8 += e2 + e3;
            const int kcl = ln >> 1, rb = (ln & 1) * 2;
            ph[kcl][rb + 0] = pack2(e0, e1);
            ph[kcl][rb + 1] = pack2(e2, e3);
        }

        // ---- O += P V (bf16, fp32 accum) over this group's 32 keys ----
        #pragma unroll
        for (int kcl = 0; kcl < 2; kcl++) {
            const int kcg = kg*2 + kcl;
            uint32_t vf[4][4];
            #pragma unroll
            for (int dp = 0; dp < 4; dp++)
                LDSM4T(vf[dp], swadr(vbh, kcg*16 + lr*8 + li, 32*dp + lc*16));
            #pragma unroll
            for (int db = 0; db < 8; db++)
                MMA(o[db], ph[kcl], vf[db>>1][(db&1)*2], vf[db>>1][(db&1)*2+1]);
        }

        b = (b == 2) ? 0 : b + 1;
    }

    // ---- reduce l within quad ----
    lg  += __shfl_xor_sync(0xffffffffu, lg, 1);
    lg  += __shfl_xor_sync(0xffffffffu, lg, 2);
    lg8 += __shfl_xor_sync(0xffffffffu, lg8, 1);
    lg8 += __shfl_xor_sync(0xffffffffu, lg8, 2);

    // ---- cross-keygroup reduction via smem (buffers are free now) ----
    float* red  = (float*)(smem + 8192);             // [4][32][32] = 16KB
    float* redl = (float*)(smem + 8192 + 16384);     // [4][32][2]
    __syncthreads();
    if (kg == 1) {
        float* dst = red + (wq4*32 + lane)*32;
        #pragma unroll
        for (int db = 0; db < 8; db++)
            #pragma unroll
            for (int t = 0; t < 4; t++) dst[db*4 + t] = o[db][t];
        redl[(wq4*32 + lane)*2 + 0] = lg;
        redl[(wq4*32 + lane)*2 + 1] = lg8;
    }
    __syncthreads();
    if (kg == 0) {
        const float* src = red + (wq4*32 + lane)*32;
        #pragma unroll
        for (int db = 0; db < 8; db++)
            #pragma unroll
            for (int t = 0; t < 4; t++) o[db][t] += src[db*4 + t];
        lg  += redl[(wq4*32 + lane)*2 + 0];
        lg8 += redl[(wq4*32 + lane)*2 + 1];

        const int gq = lane >> 2, t = lane & 3;
        const int n = qb*64 + wq4*16 + gq;
        #pragma unroll
        for (int db = 0; db < 8; db++) {
            int d = db*8 + 2*t;
            *reinterpret_cast<float2*>(&g_opart[part][n][d])     = make_float2(o[db][0], o[db][1]);
            *reinterpret_cast<float2*>(&g_opart[part][n + 8][d]) = make_float2(o[db][2], o[db][3]);
        }
        if (t == 0) {
            g_lpart[part][n]     = lg;
            g_lpart[part][n + 8] = lg8;
        }
    }
}

// ---------------- Kernel 3: combine halves + output projection (R13 known-good) -----
__global__ void __launch_bounds__(256) proj_kernel(
    const float* __restrict__ wo, const float* __restrict__ bo,
    float* __restrict__ out)
{
    __shared__ float wt[64*65];
    __shared__ float bs[64];
    __shared__ float os[32*64];
    __shared__ float linv[32];
    const int tid = threadIdx.x;
    const int row0 = blockIdx.x * 32;
    for (int i = tid; i < 4096; i += 256)
        wt[(i >> 6)*65 + (i & 63)] = wo[i];
    if (tid < 64) bs[tid] = bo[tid];
    if (tid < 32) {
        int n = row0 + tid;
        linv[tid] = 1.0f / (g_lpart[0][n] + g_lpart[1][n]);
    }
    __syncthreads();
    for (int i = tid; i < 2048; i += 256) {
        int row = i >> 6, d = i & 63;
        int n = row0 + row;
        os[i] = (g_opart[0][n][d] + g_opart[1][n][d]) * linv[row];
    }
    __syncthreads();

    for (int tI = tid; tI < 2048; tI += 256) {
        int row = tI >> 6, col = tI & 63;
        float acc = bs[col];
        const float* wrow = &wt[col*65];
        const float* orow = &os[row*64];
        #pragma unroll
        for (int d = 0; d < 64; d++)
            acc = fmaf(orow[d], wrow[d], acc);
        out[(row0 + row)*64 + col] = acc;
    }
}

// ---------------- launch ----------------
extern "C" void kernel_launch(void* const* d_in, const int* in_sizes, int n_in,
                              void* d_out, int out_size)
{
    const float* x  = (const float*)d_in[0];
    const float* wq = (const float*)d_in[1];
    const float* bq = (const float*)d_in[2];
    const float* wk = (const float*)d_in[3];
    const float* bk = (const float*)d_in[4];
    const float* wv = (const float*)d_in[5];
    const float* bv = (const float*)d_in[6];
    const float* th = (const float*)d_in[7];
    const float* wo = (const float*)d_in[8];
    const float* bo = (const float*)d_in[9];
    float* out = (float*)d_out;

    cudaFuncSetAttribute(flash_kernel, cudaFuncAttributeMaxDynamicSharedMemorySize, SMEM_FLASH);

    qkv_kernel<<<dim3(NTOK/64, 2), 256>>>(x, wq, bq, wk, bk, wv, bv, th);
    flash_kernel<<<256, 256, SMEM_FLASH>>>();
    proj_kernel<<<NTOK/32, 256>>>(wo, bo, out);
}